// round 6
// baseline (speedup 1.0000x reference)
#include <cuda_runtime.h>
#include <cuda_bf16.h>
#include <cstdint>

// DeterministicLattice: ring-stencil fusion + 5 nonlinear outputs.
// R6 (= R2..R5 resubmit; four broker timeouts, still unmeasured):
//   - evict-first streaming stores (__stcs) for the 640MB output stream so
//     the 128MB input working set keeps L2 for the 3x ring reuse
//   - 2 float4 per thread -> 6 front-batched LDG.128 (MLP 6)
//
// N=65536 rows (power of two -> ring via & mask), D=512 cols.
// Mandatory DRAM traffic: 128MB in + 640MB out = 768MB. Floor @8TB/s = 96us.
// Baseline R1: 125.2us @ DRAM 77.5% (6.15 TB/s). Target ~110-115us.

#define NODES      65536
#define DIMV       512
#define V4_PER_ROW (DIMV / 4)            // 128
#define TOTAL_V4   (NODES * V4_PER_ROW)  // 8388608
#define OUT_STRIDE_V4 TOTAL_V4           // one full output plane, in float4 units

__device__ __forceinline__ float tanh_ap(float x) {
    float y;
    asm("tanh.approx.f32 %0, %1;" : "=f"(y) : "f"(x));
    return y;
}

struct Outs { float4 o0, o1, o2, o3, o4; };

__device__ __forceinline__ Outs engine4(float4 xc, float4 xl, float4 xr) {
    const float PHI      = 1.6180339887498949f;
    const float INV_PHI  = 0.6180339887498949f;   // 1/PHI
    const float INV_DEN  = 0.27639320225002106f;  // 1/(PHI+2)
    const float HALF_PHI = 0.80901699437494745f;  // PHI/2

    Outs o;
    #pragma unroll
    for (int k = 0; k < 4; k++) {
        float c = (&xc.x)[k];
        float l = (&xl.x)[k];
        float r = (&xr.x)[k];

        float f = (PHI * c + l + r) * INV_DEN;

        float t      = tanh_ap(f);
        float bloom  = tanh_ap(PHI * f);
        float crown  = 0.5f + 0.5f * tanh_ap(HALF_PHI * f);  // sigmoid(PHI*f)
        float triad  = __sinf(f) * __cosf(PHI * f);
        float spiral = f * __expf(-fabsf(f) * INV_PHI);
        float ident  = f + INV_PHI * t;

        (&o.o0.x)[k] = ident;
        (&o.o1.x)[k] = bloom;
        (&o.o2.x)[k] = crown;
        (&o.o3.x)[k] = triad;
        (&o.o4.x)[k] = spiral;
    }
    return o;
}

__global__ __launch_bounds__(256)
void lattice_kernel(const float4* __restrict__ x, float4* __restrict__ out) {
    // Each thread handles 2 consecutive float4s. idx0 is even, so idx0 and
    // idx0+1 are always in the same row (V4_PER_ROW=128 is even).
    int tid  = blockIdx.x * blockDim.x + threadIdx.x;
    int idx0 = tid * 2;                       // [0, TOTAL_V4), step 2
    int row  = idx0 >> 7;
    int col  = idx0 & (V4_PER_ROW - 1);
    int up0  = ((row - 1) & (NODES - 1)) * V4_PER_ROW + col;  // roll +1
    int dn0  = ((row + 1) & (NODES - 1)) * V4_PER_ROW + col;  // roll -1

    // Front-batched loads: 6 independent LDG.128 in flight.
    float4 xc0 = __ldg(&x[idx0]);
    float4 xc1 = __ldg(&x[idx0 + 1]);
    float4 xl0 = __ldg(&x[up0]);
    float4 xl1 = __ldg(&x[up0 + 1]);
    float4 xr0 = __ldg(&x[dn0]);
    float4 xr1 = __ldg(&x[dn0 + 1]);

    Outs a = engine4(xc0, xl0, xr0);
    Outs b = engine4(xc1, xl1, xr1);

    // Streaming (evict-first) stores: output is never re-read; keep L2 for
    // the input ring reuse.
    __stcs(&out[idx0],                         a.o0);
    __stcs(&out[idx0 + 1],                     b.o0);
    __stcs(&out[idx0 +     OUT_STRIDE_V4],     a.o1);
    __stcs(&out[idx0 + 1 + OUT_STRIDE_V4],     b.o1);
    __stcs(&out[idx0 +     2 * OUT_STRIDE_V4], a.o2);
    __stcs(&out[idx0 + 1 + 2 * OUT_STRIDE_V4], b.o2);
    __stcs(&out[idx0 +     3 * OUT_STRIDE_V4], a.o3);
    __stcs(&out[idx0 + 1 + 3 * OUT_STRIDE_V4], b.o3);
    __stcs(&out[idx0 +     4 * OUT_STRIDE_V4], a.o4);
    __stcs(&out[idx0 + 1 + 4 * OUT_STRIDE_V4], b.o4);
}

extern "C" void kernel_launch(void* const* d_in, const int* in_sizes, int n_in,
                              void* d_out, int out_size) {
    const float4* x = (const float4*)d_in[0];
    float4* out = (float4*)d_out;

    const int threads = 256;
    const int blocks  = (TOTAL_V4 / 2) / threads;  // 16384
    lattice_kernel<<<blocks, threads>>>(x, out);
}

// round 7
// speedup vs baseline: 1.3632x; 1.3632x over previous
#include <cuda_runtime.h>
#include <cuda_bf16.h>
#include <cstdint>

// DeterministicLattice: ring-stencil fusion + 5 nonlinear outputs.
// R7: exact R1 structure (1 float4/thread, 32 regs, occ~80%, 125.2us measured)
//     + SINGLE change: __stcs evict-first on the 5 output stores.
// R6 post-mortem: 2x unroll raised regs 32->48, occ 79.6->51.8%, dur 167.6us.
//     Per-thread MLP batching is falsified at this occupancy; reverted.
//
// N=65536 rows (power of two -> ring via & mask), D=512 cols.
// Mandatory DRAM traffic: 128MB in + 640MB out = 768MB. Floor @8TB/s = 96us.

#define NODES      65536
#define DIMV       512
#define V4_PER_ROW (DIMV / 4)            // 128
#define TOTAL_V4   (NODES * V4_PER_ROW)  // 8388608
#define OUT_STRIDE_V4 TOTAL_V4           // one full output plane, in float4 units

__device__ __forceinline__ float tanh_ap(float x) {
    float y;
    asm("tanh.approx.f32 %0, %1;" : "=f"(y) : "f"(x));
    return y;
}

__global__ __launch_bounds__(256)
void lattice_kernel(const float4* __restrict__ x, float4* __restrict__ out) {
    const float PHI      = 1.6180339887498949f;
    const float INV_PHI  = 0.6180339887498949f;   // 1/PHI
    const float INV_DEN  = 0.27639320225002106f;  // 1/(PHI+2)
    const float HALF_PHI = 0.80901699437494745f;  // PHI/2

    int idx = blockIdx.x * blockDim.x + threadIdx.x;   // [0, TOTAL_V4)
    int row = idx >> 7;           // idx / 128
    int col = idx & (V4_PER_ROW - 1);
    int up  = ((row - 1) & (NODES - 1)) * V4_PER_ROW + col;  // roll +1
    int dn  = ((row + 1) & (NODES - 1)) * V4_PER_ROW + col;  // roll -1

    float4 xc = __ldg(&x[idx]);
    float4 xl = __ldg(&x[up]);
    float4 xr = __ldg(&x[dn]);

    float4 o0, o1, o2, o3, o4;

    #pragma unroll
    for (int k = 0; k < 4; k++) {
        float c = (&xc.x)[k];
        float l = (&xl.x)[k];
        float r = (&xr.x)[k];

        float f = (PHI * c + l + r) * INV_DEN;

        float t      = tanh_ap(f);
        float bloom  = tanh_ap(PHI * f);
        float crown  = 0.5f + 0.5f * tanh_ap(HALF_PHI * f);  // sigmoid(PHI*f)
        float triad  = __sinf(f) * __cosf(PHI * f);
        float spiral = f * __expf(-fabsf(f) * INV_PHI);
        float ident  = f + INV_PHI * t;

        (&o0.x)[k] = ident;
        (&o1.x)[k] = bloom;
        (&o2.x)[k] = crown;
        (&o3.x)[k] = triad;
        (&o4.x)[k] = spiral;
    }

    // Streaming (evict-first) stores: output is never re-read; keep L2 for
    // the input ring reuse. Only change vs the 125.2us R1 baseline.
    __stcs(&out[idx],                     o0);  // identity_next
    __stcs(&out[idx +     OUT_STRIDE_V4], o1);  // bloom
    __stcs(&out[idx + 2 * OUT_STRIDE_V4], o2);  // crown
    __stcs(&out[idx + 3 * OUT_STRIDE_V4], o3);  // triad
    __stcs(&out[idx + 4 * OUT_STRIDE_V4], o4);  // spiral
}

extern "C" void kernel_launch(void* const* d_in, const int* in_sizes, int n_in,
                              void* d_out, int out_size) {
    const float4* x = (const float4*)d_in[0];
    float4* out = (float4*)d_out;

    const int threads = 256;
    const int blocks  = TOTAL_V4 / threads;  // 32768
    lattice_kernel<<<blocks, threads>>>(x, out);
}